// round 16
// baseline (speedup 1.0000x reference)
#include <cuda_runtime.h>
#include <cuda_bf16.h>
#include <stdint.h>

#define NB 512
#define NS 2048
#define NE 64
#define NP 32
#define NH 64
#define TILE 128
#define NQ 8              /* sequence split factor */
#define NTILES_Q 2        /* tiles per CTA = 16/NQ */
#define NWARP 4
#define NEG_F (-4294967296.0f)   /* fp32(-2^32+1) */

__device__ uint4  g_wf[6 * 8 * 32];        // W fragments, built once (24 KB, L1/L2-hot)
__device__ float2 g_cz[NB * NH];           // {c[b][h], z[h]} per batch row
__device__ float  g_scr_u[NB * NQ * NH];   // scaled u partials per CTA
__device__ float  g_scr_mlr[NB * NQ * 4];  // {M, Lscaled, Rsum, pad} per CTA
__device__ int    g_cnt[NB];               // arrival counters (self-resetting)

__device__ __forceinline__ float fast_tanh(float x) {
    float e = __expf(2.0f * x);
    return 1.0f - __fdividef(2.0f, e + 1.0f);
}

// Split two fp32 into packed bf16-hi pair (truncation) + bf16-lo pair (residual, RN).
__device__ __forceinline__ void cvt_pair(float x, float y, uint32_t &hi, uint32_t &lo) {
    uint32_t bx = __float_as_uint(x), by = __float_as_uint(y);
    hi = __byte_perm(bx, by, 0x7632);          // {bf16(y), bf16(x)}, x in low half
    float lx = x - __uint_as_float(bx & 0xffff0000u);
    float ly = y - __uint_as_float(by & 0xffff0000u);
    asm("cvt.rn.bf16x2.f32 %0, %1, %2;" : "=r"(lo) : "f"(ly), "f"(lx));
}

#define MMA_BF16(d, a, bb0, bb1)                                          \
    asm volatile(                                                          \
        "mma.sync.aligned.m16n8k16.row.col.f32.bf16.bf16.f32 "             \
        "{%0,%1,%2,%3},{%4,%5,%6,%7},{%8,%9},{%0,%1,%2,%3};"               \
        : "+f"((d)[0]), "+f"((d)[1]), "+f"((d)[2]), "+f"((d)[3])           \
        : "r"((a)[0]), "r"((a)[1]), "r"((a)[2]), "r"((a)[3]),              \
          "r"(bb0), "r"(bb1))

// ---------- prep: 268 blocks, flat critical path ----------
// blocks [0,12): one wf entry per thread; blocks [12,268): cz for 2 batch rows each
__global__ void __launch_bounds__(128) i2i_prep(
    const float* __restrict__ target, const float* __restrict__ Wp,
    const float* __restrict__ We, const float* __restrict__ Wc,
    const float* __restrict__ bias, const float* __restrict__ zv)
{
    const int tid = threadIdx.x;
    if (blockIdx.x < 12) {
        const int i = blockIdx.x * 128 + tid;   // wf entry index
        int li = i & 31;
        int nt = (i >> 5) & 7;
        int ks = i >> 8;
        int gg = li >> 2, tt = li & 3;
        int n0 = nt * 8 + gg;
        int k0 = ks * 16 + 4 * tt;              // 4 consecutive k per lane
        #define GETW(k) (((k) < NE) ? We[(k) * NH + n0] : Wp[((k) - NE) * NH + n0])
        float w00 = GETW(k0),     w01 = GETW(k0 + 1);
        float w10 = GETW(k0 + 2), w11 = GETW(k0 + 3);
        #undef GETW
        uint32_t bh0, bl0, bh1, bl1;
        cvt_pair(w00, w01, bh0, bl0);
        cvt_pair(w10, w11, bh1, bl1);
        g_wf[i] = make_uint4(bh0, bh1, bl0, bl1);
    } else {
        const int b = (blockIdx.x - 12) * 2 + (tid >> 6);
        const int h = tid & 63;
        float a = bias[h];
        const float* tg = target + b * 64;
        #pragma unroll 8
        for (int d = 0; d < 64; d++) a = fmaf(tg[d], Wc[d * NH + h], a);
        g_cz[b * NH + h] = make_float2(a, zv[h]);
    }
}

// ---------- main: one CTA per (batch row, sequence eighth); last CTA merges ----------
__global__ void __launch_bounds__(128, 4) i2i_kernel(
    const float* __restrict__ seq_items, const float* __restrict__ seq_pos,
    const int* __restrict__ seq_len, float* __restrict__ out)
{
    __shared__ float4 czcz[32];                // {c[2j],z[2j],c[2j+1],z[2j+1]}
    __shared__ float  a_w[NWARP][32];          // warp-private score slice
    __shared__ float  u_sm[NWARP * 64];        // u partials per warp
    __shared__ float  mlr[NWARP][3];           // per-warp m, l, r
    __shared__ int    s_last;

    const int q = blockIdx.x;                  // sequence eighth
    const int b = blockIdx.y;                  // batch row
    const int cta = b * NQ + q;
    const int tid = threadIdx.x;
    const int warp = tid >> 5, lane = tid & 31;
    const int g = lane >> 2, tig = lane & 3;
    const uint4* __restrict__ gw = g_wf;

    // ---- tiny prologue: cz only (wf read directly from global in the loop) ----
    if (tid < NH) ((float2*)czcz)[tid] = g_cz[b * NH + tid];
    __syncthreads();

    const int L = seq_len[b];
    const float* Xi = seq_items + (size_t)b * NS * NE;
    const float* Xp = seq_pos   + (size_t)b * NS * NP;

    // warp state: m warp-uniform; l, r PER-LANE (reduced once at the end)
    float m = -__int_as_float(0x7f800000);
    float l = 0.f, r = 0.f;
    float4 u4 = make_float4(0.f, 0.f, 0.f, 0.f);
    const int c16 = lane & 15, hh = lane >> 4;

    for (int tile = 0; tile < NTILES_Q; ++tile) {
        float acc[2][8][4];
        #pragma unroll
        for (int mi = 0; mi < 2; mi++)
            #pragma unroll
            for (int nt = 0; nt < 8; nt++)
                #pragma unroll
                for (int qq = 0; qq < 4; qq++) acc[mi][nt][qq] = 0.f;

        const int trow = (q * NTILES_Q + tile) * TILE + warp * 32;

        #pragma unroll
        for (int ks = 0; ks < 6; ks++) {
            // ---- A fragments: ONE float4 per row (k-permutation matches wf) ----
            uint32_t Ah[2][4], Al[2][4];
            const float* bp = (ks < 4) ? Xi : Xp;
            const int ld = (ks < 4) ? NE : NP;
            const int ci = ((ks < 4) ? ks * 16 : (ks - 4) * 16) + 4 * tig;
            #pragma unroll
            for (int mi = 0; mi < 2; mi++) {
                const float* p0 = bp + (size_t)(trow + mi * 16 + g) * ld + ci;
                float4 v0 = *(const float4*)p0;
                float4 v1 = *(const float4*)(p0 + (size_t)8 * ld);
                cvt_pair(v0.x, v0.y, Ah[mi][0], Al[mi][0]);
                cvt_pair(v1.x, v1.y, Ah[mi][1], Al[mi][1]);
                cvt_pair(v0.z, v0.w, Ah[mi][2], Al[mi][2]);
                cvt_pair(v1.z, v1.w, Ah[mi][3], Al[mi][3]);
            }

            // ---- split-term-outer MMA ordering; B fragments straight from L1-hot global ----
            #pragma unroll
            for (int half = 0; half < 2; half++) {
                uint4 f[4];
                #pragma unroll
                for (int j = 0; j < 4; j++)
                    f[j] = __ldg(gw + (ks * 8 + half * 4 + j) * 32 + lane);

                #pragma unroll
                for (int j = 0; j < 4; j++)
                    #pragma unroll
                    for (int mi = 0; mi < 2; mi++)
                        MMA_BF16(acc[mi][half * 4 + j], Ah[mi], f[j].x, f[j].y);
                #pragma unroll
                for (int j = 0; j < 4; j++)
                    #pragma unroll
                    for (int mi = 0; mi < 2; mi++)
                        MMA_BF16(acc[mi][half * 4 + j], Al[mi], f[j].x, f[j].y);
                #pragma unroll
                for (int j = 0; j < 4; j++)
                    #pragma unroll
                    for (int mi = 0; mi < 2; mi++)
                        MMA_BF16(acc[mi][half * 4 + j], Ah[mi], f[j].z, f[j].w);
            }
        }

        // ---- epilogue: a[t] = sum_h z_h * tanh(Y[t,h] + c_h) ----
        #pragma unroll
        for (int mi = 0; mi < 2; mi++) {
            float part0 = 0.f, part1 = 0.f;
            #pragma unroll
            for (int nt = 0; nt < 8; nt++) {
                float4 cz = czcz[nt * 4 + tig];
                part0 += cz.y * fast_tanh(acc[mi][nt][0] + cz.x) + cz.w * fast_tanh(acc[mi][nt][1] + cz.z);
                part1 += cz.y * fast_tanh(acc[mi][nt][2] + cz.x) + cz.w * fast_tanh(acc[mi][nt][3] + cz.z);
            }
            part0 += __shfl_xor_sync(0xffffffffu, part0, 1);
            part0 += __shfl_xor_sync(0xffffffffu, part0, 2);
            part1 += __shfl_xor_sync(0xffffffffu, part1, 1);
            part1 += __shfl_xor_sync(0xffffffffu, part1, 2);
            if (tig == 0) {
                a_w[warp][mi * 16 + g]     = part0;
                a_w[warp][mi * 16 + 8 + g] = part1;
            }
        }
        __syncwarp();

        // ---- warp-local online softmax (only the MAX is reduced per tile) ----
        float av  = a_w[warp][lane];
        bool inm  = (trow + lane) < L;
        float amv = inm ? av : NEG_F;
        r += inm ? av : 0.f;                 // per-lane raw sum
        float mx = amv;
        #pragma unroll
        for (int o = 16; o > 0; o >>= 1)
            mx = fmaxf(mx, __shfl_xor_sync(0xffffffffu, mx, o));
        float m_new = fmaxf(m, mx);
        float sc = __expf(m - m_new);
        float p_own = __expf(amv - m_new);
        l = l * sc + p_own;                  // per-lane l
        m = m_new;

        // ---- u accumulation, float4 ----
        u4.x *= sc; u4.y *= sc; u4.z *= sc; u4.w *= sc;
        const float* xr = Xi + (size_t)(trow + hh) * NE + 4 * c16;
        #pragma unroll
        for (int t = 0; t < 16; t++) {
            float pf = __shfl_sync(0xffffffffu, p_own, hh + 2 * t);
            float4 v = *(const float4*)(xr + (size_t)(2 * t) * NE);
            u4.x = fmaf(pf, v.x, u4.x);
            u4.y = fmaf(pf, v.y, u4.y);
            u4.z = fmaf(pf, v.z, u4.z);
            u4.w = fmaf(pf, v.w, u4.w);
        }
    }

    // ---- end-of-kernel: reduce per-lane l/r, combine halves, CTA merge ----
    #pragma unroll
    for (int o = 16; o > 0; o >>= 1) {
        l += __shfl_xor_sync(0xffffffffu, l, o);
        r += __shfl_xor_sync(0xffffffffu, r, o);
    }
    u4.x += __shfl_xor_sync(0xffffffffu, u4.x, 16);
    u4.y += __shfl_xor_sync(0xffffffffu, u4.y, 16);
    u4.z += __shfl_xor_sync(0xffffffffu, u4.z, 16);
    u4.w += __shfl_xor_sync(0xffffffffu, u4.w, 16);
    if (hh == 0) ((float4*)(u_sm + warp * 64))[c16] = u4;
    if (lane == 0) { mlr[warp][0] = m; mlr[warp][1] = l; mlr[warp][2] = r; }
    __syncthreads();

    if (tid < NH) {
        float M = fmaxf(fmaxf(mlr[0][0], mlr[1][0]), fmaxf(mlr[2][0], mlr[3][0]));
        float S = 0.f, Ls = 0.f;
        #pragma unroll
        for (int w = 0; w < NWARP; w++) {
            float e = __expf(mlr[w][0] - M);
            S  = fmaf(u_sm[w * 64 + tid], e, S);
            Ls = fmaf(mlr[w][1], e, Ls);
        }
        g_scr_u[cta * NH + tid] = S;
        if (tid == 0) {
            g_scr_mlr[cta * 4 + 0] = M;
            g_scr_mlr[cta * 4 + 1] = Ls;
            g_scr_mlr[cta * 4 + 2] = mlr[0][2] + mlr[1][2] + mlr[2][2] + mlr[3][2];
        }
    }

    // ---- last CTA of this batch row performs the cross-split flash merge ----
    __threadfence();
    __syncthreads();
    if (tid == 0) {
        int old = atomicAdd(&g_cnt[b], 1);
        s_last = (old == NQ - 1);
        __threadfence();
    }
    __syncthreads();
    if (s_last) {
        if (tid < NH) {
            float mq[NQ], lq[NQ], rq[NQ];
            #pragma unroll
            for (int qv = 0; qv < NQ; qv++) {
                mq[qv] = g_scr_mlr[(b * NQ + qv) * 4 + 0];
                lq[qv] = g_scr_mlr[(b * NQ + qv) * 4 + 1];
                rq[qv] = g_scr_mlr[(b * NQ + qv) * 4 + 2];
            }
            float M = NEG_F;
            #pragma unroll
            for (int qv = 0; qv < NQ; qv++) M = fmaxf(M, mq[qv]);
            float S = 0.f, Ls = 0.f, R = 0.f;
            #pragma unroll
            for (int qv = 0; qv < NQ; qv++) {
                float e = __expf(mq[qv] - M);
                S  = fmaf(g_scr_u[(b * NQ + qv) * NH + tid], e, S);
                Ls = fmaf(lq[qv], e, Ls);
                R += rq[qv];
            }
            out[b * NH + tid] = S / Ls;
            if (tid == 0) out[NB * NH + b] = R;
        }
        if (tid == 64) g_cnt[b] = 0;   // reset for next graph replay
    }
}

extern "C" void kernel_launch(void* const* d_in, const int* in_sizes, int n_in,
                              void* d_out, int out_size) {
    const float* seq_items = (const float*)d_in[0];
    const float* seq_pos   = (const float*)d_in[1];
    const float* target    = (const float*)d_in[2];
    const float* Wp        = (const float*)d_in[3];
    const float* We        = (const float*)d_in[4];
    const float* Wc        = (const float*)d_in[5];
    const float* bias      = (const float*)d_in[6];
    const float* zv        = (const float*)d_in[7];
    const int*   seq_len   = (const int*)d_in[8];
    float* out = (float*)d_out;

    i2i_prep<<<268, 128>>>(target, Wp, We, Wc, bias, zv);
    dim3 grid(NQ, NB);
    i2i_kernel<<<grid, 128>>>(seq_items, seq_pos, seq_len, out);
}

// round 17
// speedup vs baseline: 1.1051x; 1.1051x over previous
#include <cuda_runtime.h>
#include <cuda_bf16.h>
#include <stdint.h>

#define NB 512
#define NS 2048
#define NE 64
#define NP 32
#define NH 64
#define TILE 128
#define NQ 8              /* sequence split factor */
#define NTILES_Q 2        /* tiles per CTA = 16/NQ */
#define NWARP 4
#define NEG_F (-4294967296.0f)   /* fp32(-2^32+1) */

__device__ uint4  g_wf[6 * 8 * 32];        // W fragments, built once
__device__ float2 g_cz[NB * NH];           // {c[b][h], z[h]} per batch row
__device__ float  g_scr_u[NB * NQ * NH];   // scaled u partials per CTA
__device__ float  g_scr_mlr[NB * NQ * 4];  // {M, Lscaled, Rsum, pad} per CTA

__device__ __forceinline__ float fast_tanh(float x) {
    float e = __expf(2.0f * x);
    return 1.0f - __fdividef(2.0f, e + 1.0f);
}

// Split two fp32 into packed bf16-hi pair (truncation) + bf16-lo pair (residual, RN).
__device__ __forceinline__ void cvt_pair(float x, float y, uint32_t &hi, uint32_t &lo) {
    uint32_t bx = __float_as_uint(x), by = __float_as_uint(y);
    hi = __byte_perm(bx, by, 0x7632);          // {bf16(y), bf16(x)}, x in low half
    float lx = x - __uint_as_float(bx & 0xffff0000u);
    float ly = y - __uint_as_float(by & 0xffff0000u);
    asm("cvt.rn.bf16x2.f32 %0, %1, %2;" : "=r"(lo) : "f"(ly), "f"(lx));
}

#define MMA_BF16(d, a, bb0, bb1)                                          \
    asm volatile(                                                          \
        "mma.sync.aligned.m16n8k16.row.col.f32.bf16.bf16.f32 "             \
        "{%0,%1,%2,%3},{%4,%5,%6,%7},{%8,%9},{%0,%1,%2,%3};"               \
        : "+f"((d)[0]), "+f"((d)[1]), "+f"((d)[2]), "+f"((d)[3])           \
        : "r"((a)[0]), "r"((a)[1]), "r"((a)[2]), "r"((a)[3]),              \
          "r"(bb0), "r"(bb1))

// ---------- prep: 268 blocks, flat critical path ----------
// blocks [0,12): one wf entry per thread; blocks [12,268): cz for 2 batch rows each
__global__ void __launch_bounds__(128) i2i_prep(
    const float* __restrict__ target, const float* __restrict__ Wp,
    const float* __restrict__ We, const float* __restrict__ Wc,
    const float* __restrict__ bias, const float* __restrict__ zv)
{
    const int tid = threadIdx.x;
    if (blockIdx.x < 12) {
        const int i = blockIdx.x * 128 + tid;   // wf entry index
        int li = i & 31;
        int nt = (i >> 5) & 7;
        int ks = i >> 8;
        int gg = li >> 2, tt = li & 3;
        int n0 = nt * 8 + gg;
        int k0 = ks * 16 + 4 * tt;              // 4 consecutive k per lane
        #define GETW(k) (((k) < NE) ? We[(k) * NH + n0] : Wp[((k) - NE) * NH + n0])
        float w00 = GETW(k0),     w01 = GETW(k0 + 1);
        float w10 = GETW(k0 + 2), w11 = GETW(k0 + 3);
        #undef GETW
        uint32_t bh0, bl0, bh1, bl1;
        cvt_pair(w00, w01, bh0, bl0);
        cvt_pair(w10, w11, bh1, bl1);
        g_wf[i] = make_uint4(bh0, bh1, bl0, bl1);
    } else {
        const int b = (blockIdx.x - 12) * 2 + (tid >> 6);
        const int h = tid & 63;
        float a = bias[h];
        const float* tg = target + b * 64;
        #pragma unroll 8
        for (int d = 0; d < 64; d++) a = fmaf(tg[d], Wc[d * NH + h], a);
        g_cz[b * NH + h] = make_float2(a, zv[h]);
    }
}

// ---------- main: one CTA per (batch row, sequence eighth) ----------
__global__ void __launch_bounds__(128, 4) i2i_kernel(
    const float* __restrict__ seq_items, const float* __restrict__ seq_pos,
    const int* __restrict__ seq_len)
{
    __shared__ uint4  wf[6 * 8 * 32];          // 24 KB staged from g_wf
    __shared__ float4 czcz[32];                // {c[2j],z[2j],c[2j+1],z[2j+1]}
    __shared__ float  a_w[NWARP][32];          // warp-private score slice
    __shared__ float  u_sm[NWARP * 64];        // u partials per warp
    __shared__ float  mlr[NWARP][3];           // per-warp m, l, r

    const int q = blockIdx.x;                  // sequence eighth
    const int b = blockIdx.y;                  // batch row
    const int cta = b * NQ + q;
    const int tid = threadIdx.x;
    const int warp = tid >> 5, lane = tid & 31;
    const int g = lane >> 2, tig = lane & 3;

    // ---- cheap prologue: coalesced copies of precomputed state ----
    #pragma unroll
    for (int i = 0; i < 12; i++) wf[tid + i * 128] = g_wf[tid + i * 128];
    if (tid < NH) ((float2*)czcz)[tid] = g_cz[b * NH + tid];
    __syncthreads();   // only block barrier before final merge

    const int L = seq_len[b];
    const float* Xi = seq_items + (size_t)b * NS * NE;
    const float* Xp = seq_pos   + (size_t)b * NS * NP;

    // warp state: m warp-uniform; l, r PER-LANE (reduced once at the end)
    float m = -__int_as_float(0x7f800000);
    float l = 0.f, r = 0.f;
    float4 u4 = make_float4(0.f, 0.f, 0.f, 0.f);
    const int c16 = lane & 15, hh = lane >> 4;

    for (int tile = 0; tile < NTILES_Q; ++tile) {
        float acc[2][8][4];
        #pragma unroll
        for (int mi = 0; mi < 2; mi++)
            #pragma unroll
            for (int nt = 0; nt < 8; nt++)
                #pragma unroll
                for (int qq = 0; qq < 4; qq++) acc[mi][nt][qq] = 0.f;

        const int trow = (q * NTILES_Q + tile) * TILE + warp * 32;

        #pragma unroll
        for (int ks = 0; ks < 6; ks++) {
            // ---- A fragments: ONE float4 per row (k-permutation matches wf) ----
            uint32_t Ah[2][4], Al[2][4];
            const float* bp = (ks < 4) ? Xi : Xp;
            const int ld = (ks < 4) ? NE : NP;
            const int ci = ((ks < 4) ? ks * 16 : (ks - 4) * 16) + 4 * tig;
            #pragma unroll
            for (int mi = 0; mi < 2; mi++) {
                const float* p0 = bp + (size_t)(trow + mi * 16 + g) * ld + ci;
                float4 v0 = *(const float4*)p0;
                float4 v1 = *(const float4*)(p0 + (size_t)8 * ld);
                cvt_pair(v0.x, v0.y, Ah[mi][0], Al[mi][0]);
                cvt_pair(v1.x, v1.y, Ah[mi][1], Al[mi][1]);
                cvt_pair(v0.z, v0.w, Ah[mi][2], Al[mi][2]);
                cvt_pair(v1.z, v1.w, Ah[mi][3], Al[mi][3]);
            }

            // ---- split-term-outer MMA ordering (B from smem, LDS.128) ----
            #pragma unroll
            for (int half = 0; half < 2; half++) {
                uint4 f[4];
                #pragma unroll
                for (int j = 0; j < 4; j++)
                    f[j] = wf[(ks * 8 + half * 4 + j) * 32 + lane];

                #pragma unroll
                for (int j = 0; j < 4; j++)
                    #pragma unroll
                    for (int mi = 0; mi < 2; mi++)
                        MMA_BF16(acc[mi][half * 4 + j], Ah[mi], f[j].x, f[j].y);
                #pragma unroll
                for (int j = 0; j < 4; j++)
                    #pragma unroll
                    for (int mi = 0; mi < 2; mi++)
                        MMA_BF16(acc[mi][half * 4 + j], Al[mi], f[j].x, f[j].y);
                #pragma unroll
                for (int j = 0; j < 4; j++)
                    #pragma unroll
                    for (int mi = 0; mi < 2; mi++)
                        MMA_BF16(acc[mi][half * 4 + j], Ah[mi], f[j].z, f[j].w);
            }
        }

        // ---- epilogue: a[t] = sum_h z_h * tanh(Y[t,h] + c_h) ----
        #pragma unroll
        for (int mi = 0; mi < 2; mi++) {
            float part0 = 0.f, part1 = 0.f;
            #pragma unroll
            for (int nt = 0; nt < 8; nt++) {
                float4 cz = czcz[nt * 4 + tig];
                part0 += cz.y * fast_tanh(acc[mi][nt][0] + cz.x) + cz.w * fast_tanh(acc[mi][nt][1] + cz.z);
                part1 += cz.y * fast_tanh(acc[mi][nt][2] + cz.x) + cz.w * fast_tanh(acc[mi][nt][3] + cz.z);
            }
            part0 += __shfl_xor_sync(0xffffffffu, part0, 1);
            part0 += __shfl_xor_sync(0xffffffffu, part0, 2);
            part1 += __shfl_xor_sync(0xffffffffu, part1, 1);
            part1 += __shfl_xor_sync(0xffffffffu, part1, 2);
            if (tig == 0) {
                a_w[warp][mi * 16 + g]     = part0;
                a_w[warp][mi * 16 + 8 + g] = part1;
            }
        }
        __syncwarp();

        // ---- warp-local online softmax (only the MAX is reduced per tile) ----
        float av  = a_w[warp][lane];
        bool inm  = (trow + lane) < L;
        float amv = inm ? av : NEG_F;
        r += inm ? av : 0.f;                 // per-lane raw sum
        float mx = amv;
        #pragma unroll
        for (int o = 16; o > 0; o >>= 1)
            mx = fmaxf(mx, __shfl_xor_sync(0xffffffffu, mx, o));
        float m_new = fmaxf(m, mx);
        float sc = __expf(m - m_new);
        float p_own = __expf(amv - m_new);
        l = l * sc + p_own;                  // per-lane l
        m = m_new;

        // ---- u accumulation, float4 ----
        u4.x *= sc; u4.y *= sc; u4.z *= sc; u4.w *= sc;
        const float* xr = Xi + (size_t)(trow + hh) * NE + 4 * c16;
        #pragma unroll
        for (int t = 0; t < 16; t++) {
            float pf = __shfl_sync(0xffffffffu, p_own, hh + 2 * t);
            float4 v = *(const float4*)(xr + (size_t)(2 * t) * NE);
            u4.x = fmaf(pf, v.x, u4.x);
            u4.y = fmaf(pf, v.y, u4.y);
            u4.z = fmaf(pf, v.z, u4.z);
            u4.w = fmaf(pf, v.w, u4.w);
        }
    }

    // ---- end-of-kernel: reduce per-lane l/r, combine halves, CTA merge ----
    #pragma unroll
    for (int o = 16; o > 0; o >>= 1) {
        l += __shfl_xor_sync(0xffffffffu, l, o);
        r += __shfl_xor_sync(0xffffffffu, r, o);
    }
    u4.x += __shfl_xor_sync(0xffffffffu, u4.x, 16);
    u4.y += __shfl_xor_sync(0xffffffffu, u4.y, 16);
    u4.z += __shfl_xor_sync(0xffffffffu, u4.z, 16);
    u4.w += __shfl_xor_sync(0xffffffffu, u4.w, 16);
    if (hh == 0) ((float4*)(u_sm + warp * 64))[c16] = u4;
    if (lane == 0) { mlr[warp][0] = m; mlr[warp][1] = l; mlr[warp][2] = r; }
    __syncthreads();

    // ---- CTA-level flash merge -> global scratch partial ----
    if (tid < NH) {
        float M = fmaxf(fmaxf(mlr[0][0], mlr[1][0]), fmaxf(mlr[2][0], mlr[3][0]));
        float S = 0.f, Ls = 0.f;
        #pragma unroll
        for (int w = 0; w < NWARP; w++) {
            float e = __expf(mlr[w][0] - M);
            S  = fmaf(u_sm[w * 64 + tid], e, S);
            Ls = fmaf(mlr[w][1], e, Ls);
        }
        g_scr_u[cta * NH + tid] = S;
        if (tid == 0) {
            g_scr_mlr[cta * 4 + 0] = M;
            g_scr_mlr[cta * 4 + 1] = Ls;
            g_scr_mlr[cta * 4 + 2] = mlr[0][2] + mlr[1][2] + mlr[2][2] + mlr[3][2];
        }
    }
}

// Final cross-split flash merge: one block per batch row.
__global__ void __launch_bounds__(64) i2i_merge(float* __restrict__ out)
{
    const int b = blockIdx.x;
    const int tid = threadIdx.x;
    float mq[NQ], lq[NQ], rq[NQ];
    #pragma unroll
    for (int qv = 0; qv < NQ; qv++) {
        mq[qv] = g_scr_mlr[(b * NQ + qv) * 4 + 0];
        lq[qv] = g_scr_mlr[(b * NQ + qv) * 4 + 1];
        rq[qv] = g_scr_mlr[(b * NQ + qv) * 4 + 2];
    }
    float M = NEG_F;
    #pragma unroll
    for (int qv = 0; qv < NQ; qv++) M = fmaxf(M, mq[qv]);
    float S = 0.f, Ls = 0.f, R = 0.f;
    #pragma unroll
    for (int qv = 0; qv < NQ; qv++) {
        float e = __expf(mq[qv] - M);
        S  = fmaf(g_scr_u[(b * NQ + qv) * NH + tid], e, S);
        Ls = fmaf(lq[qv], e, Ls);
        R += rq[qv];
    }
    out[b * NH + tid] = S / Ls;
    if (tid == 0) out[NB * NH + b] = R;
}

extern "C" void kernel_launch(void* const* d_in, const int* in_sizes, int n_in,
                              void* d_out, int out_size) {
    const float* seq_items = (const float*)d_in[0];
    const float* seq_pos   = (const float*)d_in[1];
    const float* target    = (const float*)d_in[2];
    const float* Wp        = (const float*)d_in[3];
    const float* We        = (const float*)d_in[4];
    const float* Wc        = (const float*)d_in[5];
    const float* bias      = (const float*)d_in[6];
    const float* zv        = (const float*)d_in[7];
    const int*   seq_len   = (const int*)d_in[8];
    float* out = (float*)d_out;

    i2i_prep<<<268, 128>>>(target, Wp, We, Wc, bias, zv);
    dim3 grid(NQ, NB);
    i2i_kernel<<<grid, 128>>>(seq_items, seq_pos, seq_len);
    i2i_merge<<<NB, 64>>>(out);
}